// round 13
// baseline (speedup 1.0000x reference)
#include <cuda_runtime.h>
#include <cuda_fp16.h>
#include <mma.h>
#include <math.h>

using namespace nvcuda;

#define NN 100000
#define NPAD 100032            // NN rounded up to 64
#define EE 3200000
#define HIDC 128

// ---------------- device scratch (no allocations allowed) ----------------
__device__ int    g_flag64;
__device__ int    g_deg[NN];
__device__ float  g_dinv[NN];
__device__ int    g_rowptr[NN + 1];
__device__ int    g_cursor[NN];
__device__ int    g_src[EE];
__device__ float  g_w[EE];
__device__ float  g_h0[(size_t)NN * HIDC];
__device__ float  g_bufA[(size_t)NN * HIDC];
__device__ float  g_bufB[(size_t)NN * HIDC];
__device__ float  g_sbuf[(size_t)NN * HIDC];
__device__ __half g_h16[(size_t)NPAD * HIDC];     // fp16 gather / GEMM-A table
__device__ __half g_sbuf16[(size_t)NPAD * HIDC];  // fp16 copy of s (GEMM-A input)
__device__ __half g_w16[9 * HIDC * HIDC];         // fp16 weights: W_in, W_gcn[0..7]

// ---------------- dtype detection ----------------
__global__ void detect_kernel(const int* __restrict__ ew) {
    if (threadIdx.x == 0) {
        int allzero = 1;
        for (int i = 0; i < 256; i++) {
            if (ew[2 * i + 1] != 0) { allzero = 0; break; }
        }
        g_flag64 = allzero;
    }
}

__device__ __forceinline__ int load_idx(const int* __restrict__ ew, long long elem, int f64) {
    return f64 ? ew[2 * elem] : ew[elem];
}

// ---------------- graph build ----------------
__global__ void count_kernel(const int* __restrict__ ew) {
    int e = blockIdx.x * blockDim.x + threadIdx.x;
    if (e < EE) {
        int f64 = g_flag64;
        int c = load_idx(ew, (long long)EE + e, f64);
        if ((unsigned)c < NN) atomicAdd(&g_deg[c], 1);
    }
}

__global__ void scan_kernel() {
    __shared__ int sums[1024];
    const int T = 1024;
    int t = threadIdx.x;
    const int CH = (NN + T - 1) / T;
    int lo = t * CH;
    int hi = lo + CH;
    if (hi > NN) hi = NN;
    if (lo > NN) lo = NN;
    int s = 0;
    for (int i = lo; i < hi; i++) s += g_deg[i];
    sums[t] = s;
    __syncthreads();
    for (int off = 1; off < T; off <<= 1) {
        int v = (t >= off) ? sums[t - off] : 0;
        __syncthreads();
        sums[t] += v;
        __syncthreads();
    }
    int run = sums[t] - s;
    for (int i = lo; i < hi; i++) {
        int d = g_deg[i];
        g_rowptr[i] = run;
        g_cursor[i] = run;
        g_dinv[i]   = rsqrtf((float)(d + 1));
        run += d;
    }
    if (t == T - 1) g_rowptr[NN] = run;
}

__global__ void fill_kernel(const int* __restrict__ ew) {
    int e = blockIdx.x * blockDim.x + threadIdx.x;
    if (e < EE) {
        int f64 = g_flag64;
        int r = load_idx(ew, e, f64);
        int c = load_idx(ew, (long long)EE + e, f64);
        if ((unsigned)r < NN && (unsigned)c < NN) {
            int pos = atomicAdd(&g_cursor[c], 1);
            g_src[pos] = r;
            g_w[pos]   = g_dinv[r] * g_dinv[c];
        }
    }
}

// ---------------- weight / input conversion to fp16 ----------------
__global__ void convw_kernel(const float* __restrict__ Win,
                             const float* __restrict__ Wgcn) {
    int i = blockIdx.x * blockDim.x + threadIdx.x;   // 9*16384 total
    if (i < 9 * HIDC * HIDC) {
        float v = (i < HIDC * HIDC) ? Win[i] : Wgcn[i - HIDC * HIDC];
        g_w16[i] = __float2half_rn(v);
    }
}

__global__ void convx_kernel(const float* __restrict__ x) {
    int i = blockIdx.x * blockDim.x + threadIdx.x;   // quads
    if (i < NN * HIDC / 4) {
        float4 v = ((const float4*)x)[i];
        uint2 p;
        *(__half2*)&p.x = __floats2half2_rn(v.x, v.y);
        *(__half2*)&p.y = __floats2half2_rn(v.z, v.w);
        *(uint2*)(&g_h16[(size_t)i * 4]) = p;
    }
}

// ---------------- SpMM + residual: s = 0.9*(A_norm h) + 0.1*h0 ----------------
__global__ __launch_bounds__(256) void spmm_kernel(const __half* __restrict__ h16,
                                                   const float* __restrict__ hf,
                                                   const float* __restrict__ h0f,
                                                   float* __restrict__ sout,
                                                   __half* __restrict__ sout16) {
    int warp = (blockIdx.x * blockDim.x + threadIdx.x) >> 5;
    if (warp >= NN) return;
    int lane = threadIdx.x & 31;
    int beg = g_rowptr[warp];
    int end = g_rowptr[warp + 1];

    float4 acc = make_float4(0.f, 0.f, 0.f, 0.f);
    int e0 = beg;
    for (; e0 + 32 <= end; e0 += 32) {
        int   src = g_src[e0 + lane];
        float w   = g_w[e0 + lane];
#pragma unroll 8
        for (int j = 0; j < 32; j++) {
            int   sidx = __shfl_sync(0xffffffffu, src, j);
            float ww   = __shfl_sync(0xffffffffu, w, j);
            uint2 rv = *(const uint2*)(h16 + (size_t)sidx * HIDC + lane * 4);
            float2 f0 = __half22float2(*(const __half2*)&rv.x);
            float2 f1 = __half22float2(*(const __half2*)&rv.y);
            acc.x = fmaf(ww, f0.x, acc.x);
            acc.y = fmaf(ww, f0.y, acc.y);
            acc.z = fmaf(ww, f1.x, acc.z);
            acc.w = fmaf(ww, f1.y, acc.w);
        }
    }
    if (e0 < end) {
        int cnt = end - e0;
        int   src = 0;
        float w   = 0.f;
        if (lane < cnt) { src = g_src[e0 + lane]; w = g_w[e0 + lane]; }
        for (int j = 0; j < cnt; j++) {
            int   sidx = __shfl_sync(0xffffffffu, src, j);
            float ww   = __shfl_sync(0xffffffffu, w, j);
            uint2 rv = *(const uint2*)(h16 + (size_t)sidx * HIDC + lane * 4);
            float2 f0 = __half22float2(*(const __half2*)&rv.x);
            float2 f1 = __half22float2(*(const __half2*)&rv.y);
            acc.x = fmaf(ww, f0.x, acc.x);
            acc.y = fmaf(ww, f0.y, acc.y);
            acc.z = fmaf(ww, f1.x, acc.z);
            acc.w = fmaf(ww, f1.y, acc.w);
        }
    }
    // self loop in fp32
    float di = g_dinv[warp];
    float ws = di * di;
    float4 hv = *(const float4*)(hf + (size_t)warp * HIDC + lane * 4);
    acc.x = fmaf(ws, hv.x, acc.x);
    acc.y = fmaf(ws, hv.y, acc.y);
    acc.z = fmaf(ws, hv.z, acc.z);
    acc.w = fmaf(ws, hv.w, acc.w);

    float4 r0 = *(const float4*)(h0f + (size_t)warp * HIDC + lane * 4);
    float4 o;
    o.x = 0.9f * acc.x + 0.1f * r0.x;
    o.y = 0.9f * acc.y + 0.1f * r0.y;
    o.z = 0.9f * acc.z + 0.1f * r0.z;
    o.w = 0.9f * acc.w + 0.1f * r0.w;
    *(float4*)(sout + (size_t)warp * HIDC + lane * 4) = o;
    uint2 hp;
    *(__half2*)&hp.x = __floats2half2_rn(o.x, o.y);
    *(__half2*)&hp.y = __floats2half2_rn(o.z, o.w);
    *(uint2*)(sout16 + (size_t)warp * HIDC + lane * 4) = hp;
}

// ---------------- tensor-core GEMM: out = cs*Sf + cw*(S16@W16) (+bias)(relu) ----------------
// Block 64 rows x 128 cols, 8 warps in 4m x 2n grid; warp = m16 x n64 (4 wmma frags).
// A/B fragments straight from global (A read once; W16 is 32KB, L1-hot).
__global__ __launch_bounds__(256) void mma_gemm_kernel(const __half* __restrict__ S16,
                                                       const float* __restrict__ Sf,
                                                       const __half* __restrict__ W16,
                                                       const float* __restrict__ bias,
                                                       float cs, float cw, int relu,
                                                       float* __restrict__ out,
                                                       __half* __restrict__ out16) {
    __shared__ float sC[64 * 128];
    int tid  = threadIdx.x;
    int warp = tid >> 5;
    int mw = warp & 3;          // 0..3 -> 16-row group
    int nw = warp >> 2;         // 0..1 -> 64-col group
    int row0 = blockIdx.x * 64;

    wmma::fragment<wmma::accumulator, 16, 16, 16, float> c[4];
#pragma unroll
    for (int j = 0; j < 4; j++) wmma::fill_fragment(c[j], 0.f);

    const __half* Abase = S16 + (size_t)(row0 + mw * 16) * HIDC;
#pragma unroll
    for (int k = 0; k < 8; k++) {
        wmma::fragment<wmma::matrix_a, 16, 16, 16, __half, wmma::row_major> a;
        wmma::load_matrix_sync(a, Abase + k * 16, HIDC);
#pragma unroll
        for (int j = 0; j < 4; j++) {
            wmma::fragment<wmma::matrix_b, 16, 16, 16, __half, wmma::row_major> b;
            wmma::load_matrix_sync(b, W16 + (size_t)k * 16 * HIDC + nw * 64 + j * 16, HIDC);
            wmma::mma_sync(c[j], a, b, c[j]);
        }
    }
#pragma unroll
    for (int j = 0; j < 4; j++)
        wmma::store_matrix_sync(&sC[(mw * 16) * 128 + nw * 64 + j * 16], c[j], 128,
                                wmma::mem_row_major);
    __syncthreads();

    // epilogue: thread = 8 rows x 4 cols
    int lane  = tid & 31;
    int rbase = warp * 8;
    int col   = lane * 4;
    float4 b4 = make_float4(0.f, 0.f, 0.f, 0.f);
    if (bias) b4 = *(const float4*)(bias + col);

#pragma unroll
    for (int r = 0; r < 8; r++) {
        int grow = row0 + rbase + r;
        if (grow >= NN) break;
        float4 o = *(float4*)&sC[(rbase + r) * 128 + col];
        o.x *= cw; o.y *= cw; o.z *= cw; o.w *= cw;
        if (cs != 0.f) {
            float4 sv = *(const float4*)(Sf + (size_t)grow * HIDC + col);
            o.x = fmaf(cs, sv.x, o.x);
            o.y = fmaf(cs, sv.y, o.y);
            o.z = fmaf(cs, sv.z, o.z);
            o.w = fmaf(cs, sv.w, o.w);
        }
        o.x += b4.x; o.y += b4.y; o.z += b4.z; o.w += b4.w;
        if (relu) {
            o.x = fmaxf(o.x, 0.f); o.y = fmaxf(o.y, 0.f);
            o.z = fmaxf(o.z, 0.f); o.w = fmaxf(o.w, 0.f);
        }
        *(float4*)(out + (size_t)grow * HIDC + col) = o;
        if (out16) {
            uint2 hp;
            *(__half2*)&hp.x = __floats2half2_rn(o.x, o.y);
            *(__half2*)&hp.y = __floats2half2_rn(o.z, o.w);
            *(uint2*)(out16 + (size_t)grow * HIDC + col) = hp;
        }
    }
}

// ---------------- output projection ----------------
__global__ __launch_bounds__(256) void outproj_kernel(const float* __restrict__ h,
                                                      const float* __restrict__ Wout,
                                                      const float* __restrict__ bout,
                                                      float* __restrict__ out) {
    int warp = (blockIdx.x * blockDim.x + threadIdx.x) >> 5;
    if (warp >= NN) return;
    int lane = threadIdx.x & 31;
    float4 hv = *(const float4*)(h + (size_t)warp * HIDC + lane * 4);
    float4 wv = *(const float4*)(Wout + lane * 4);
    float a = hv.x * wv.x + hv.y * wv.y + hv.z * wv.z + hv.w * wv.w;
#pragma unroll
    for (int off = 16; off; off >>= 1) a += __shfl_xor_sync(0xffffffffu, a, off);
    if (lane == 0) out[warp] = a + bout[0];
}

// ---------------- launch ----------------
extern "C" void kernel_launch(void* const* d_in, const int* in_sizes, int n_in,
                              void* d_out, int out_size) {
    const float* x     = (const float*)d_in[0];
    const float* W_in  = (const float*)d_in[2];
    const float* b_in  = (const float*)d_in[3];
    const float* W_gcn = (const float*)d_in[4];
    const float* W_out = (const float*)d_in[5];
    const float* b_out = (const float*)d_in[6];
    const int*   ei    = (const int*)d_in[7];
    float* out = (float*)d_out;

    void *pDeg, *pH0, *pA, *pB, *pS, *pH16, *pS16, *pW16;
    cudaGetSymbolAddress(&pDeg, g_deg);
    cudaGetSymbolAddress(&pH0,  g_h0);
    cudaGetSymbolAddress(&pA,   g_bufA);
    cudaGetSymbolAddress(&pB,   g_bufB);
    cudaGetSymbolAddress(&pS,   g_sbuf);
    cudaGetSymbolAddress(&pH16, g_h16);
    cudaGetSymbolAddress(&pS16, g_sbuf16);
    cudaGetSymbolAddress(&pW16, g_w16);
    float*  h0    = (float*)pH0;
    float*  bufA  = (float*)pA;
    float*  bufB  = (float*)pB;
    float*  sbuf  = (float*)pS;
    __half* h16   = (__half*)pH16;
    __half* s16   = (__half*)pS16;
    __half* w16   = (__half*)pW16;

    // graph build
    detect_kernel<<<1, 32>>>(ei);
    cudaMemsetAsync(pDeg, 0, NN * sizeof(int), 0);
    count_kernel<<<EE / 256, 256>>>(ei);
    scan_kernel<<<1, 1024>>>();
    fill_kernel<<<EE / 256, 256>>>(ei);

    // fp16 conversions
    convw_kernel<<<(9 * HIDC * HIDC + 255) / 256, 256>>>(W_in, W_gcn);
    convx_kernel<<<(NN * HIDC / 4 + 255) / 256, 256>>>(x);

    const int GB = NPAD / 64;   // 1563

    // input projection: h0 = x @ W_in + b_in  (reads x16 in g_h16, writes h0 + h16)
    mma_gemm_kernel<<<GB, 256>>>(h16, x, w16, b_in, 0.f, 1.f, 0, h0, h16);

    const float* cur = h0;
    for (int i = 0; i < 8; i++) {
        spmm_kernel<<<NN / 8, 256>>>(h16, cur, h0, sbuf, s16);
        float beta = logf(0.5f / (float)(i + 1) + 1.0f);
        float* dst = (i & 1) ? bufB : bufA;
        __half* t16 = (i == 7) ? nullptr : h16;
        mma_gemm_kernel<<<GB, 256>>>(s16, sbuf, w16 + (size_t)(i + 1) * HIDC * HIDC,
                                     nullptr, 1.0f - beta, beta, 1, dst, t16);
        cur = dst;
    }

    outproj_kernel<<<NN / 8, 256>>>(cur, W_out, b_out, out);
}